// round 3
// baseline (speedup 1.0000x reference)
#include <cuda_runtime.h>
#include <math.h>

#define H 512
#define W 512
#define NS 14            // number of gaussian scales (K+1)
#define NK 13            // number of DoG planes (K)
#define MAXR 43
#define NROWS (NK*H)
#define THRESH 0.001f
#define MAXPEAKS 32768

// ---- scratch (static device memory; no allocations allowed) ----
__device__ double d_tmp[NS*H*W];      // after horizontal blur (fp64)
__device__ float  d_g[NS*H*W];        // gaussian pyramid, rounded to fp32 (matches ref's g)
__device__ float  d_dog[NK*H*W];      // DoG * sigma (fp32, computed from fp32 g like ref)
__device__ double d_k1d[NS*96];       // 1D kernels in fp64 (zero padded to 96)
__device__ int    d_rad[NS];
__device__ float  d_sig[NS];
__device__ unsigned d_maskw[NROWS*16];// 512-bit peak mask per (k,y) row
__device__ int    d_rowcnt[NROWS];    // counts, then exclusive offsets

// ---------------------------------------------------------------
// Build the normalized 1D gaussian kernels (fp64):
// g1[j] = 1/(s*sqrt(2pi)) * exp(-(((j-mean)/(2s))^2)), normalized by sum.
// 2D kernel = outer(g1n,g1n) => separable H+V conv == full 2D conv.
// ---------------------------------------------------------------
__global__ void build_kernels_k(const float* __restrict__ sigma_list) {
    int i   = blockIdx.x;       // scale
    int tid = threadIdx.x;      // 128 threads
    float sf = sigma_list[i];
    double s = (double)sf;
    int r   = (int)floor(4.0 * s + 0.5);   // TRUNCATE=4
    int n   = 2 * r + 1;
    __shared__ double tmp[96];
    __shared__ double ssum;
    if (tid < n) {
        double mean = 0.5 * (double)(n - 1);
        double d = ((double)tid - mean) / (2.0 * s);
        tmp[tid] = exp(-(d * d));   // prefactor cancels in normalization
    }
    __syncthreads();
    if (tid == 0) {
        double acc = 0.0;
        for (int j = 0; j < n; j++) acc += tmp[j];
        ssum = acc;
        d_rad[i] = r;
        d_sig[i] = sf;
    }
    __syncthreads();
    if (tid < 96) d_k1d[i*96 + tid] = (tid < n) ? tmp[tid] / ssum : 0.0;
}

// ---------------------------------------------------------------
// Horizontal pass (fp64 accumulation): one block per (row, scale).
// ---------------------------------------------------------------
__global__ void hblur_k(const float* __restrict__ x) {
    int y  = blockIdx.x;
    int sc = blockIdx.y;
    int r  = d_rad[sc];
    int n  = 2 * r + 1;
    __shared__ float  srow[W + 2*MAXR];
    __shared__ double sk[96];
    int tid = threadIdx.x;
    for (int i = tid; i < W + 2*r; i += blockDim.x) {
        int xx = i - r;
        srow[i] = (xx >= 0 && xx < W) ? x[y*W + xx] : 0.f;
    }
    for (int i = tid; i < n; i += blockDim.x) sk[i] = d_k1d[sc*96 + i];
    __syncthreads();
    double* outp = d_tmp + (size_t)(sc*H + y) * W;
    for (int xo = tid; xo < W; xo += blockDim.x) {
        double acc = 0.0;
        for (int d = 0; d < n; d++) acc += (double)srow[xo + d] * sk[d];
        outp[xo] = acc;
    }
}

// ---------------------------------------------------------------
// Vertical pass (fp64): 32-wide x-strip, 32-row output tile per block.
// Result rounded to fp32 (matches reference's materialized fp32 g).
// ---------------------------------------------------------------
#define VTX 32
#define VTY 32
__global__ void vblur_k() {
    int sc = blockIdx.z;
    int x0 = blockIdx.x * VTX;
    int y0 = blockIdx.y * VTY;
    int r  = d_rad[sc];
    int n  = 2 * r + 1;
    __shared__ double tile[(VTY + 2*MAXR) * VTX];   // 118*32*8 = 30208 B
    __shared__ double sk[96];
    int tid = threadIdx.x + threadIdx.y * VTX;      // blockDim (32,8) = 256
    int nth = VTX * 8;
    int rows = VTY + 2 * r;
    const double* inp = d_tmp + (size_t)sc * H * W;
    for (int i = tid; i < rows * VTX; i += nth) {
        int rr = i / VTX, cc = i % VTX;
        int gy = y0 - r + rr;
        tile[i] = (gy >= 0 && gy < H) ? inp[gy*W + x0 + cc] : 0.0;
    }
    for (int i = tid; i < n; i += nth) sk[i] = d_k1d[sc*96 + i];
    __syncthreads();
    float* outp = d_g + (size_t)sc * H * W;
    int tx = threadIdx.x;
    for (int yo = threadIdx.y; yo < VTY; yo += 8) {
        double acc = 0.0;
        for (int d = 0; d < n; d++) acc += tile[(yo + d)*VTX + tx] * sk[d];
        outp[(y0 + yo)*W + x0 + tx] = (float)acc;
    }
}

// ---------------------------------------------------------------
// DoG in fp32, exactly like reference: dog[k] = (g[k]-g[k+1])*sigma[k]
// ---------------------------------------------------------------
__global__ void dog_k() {
    int idx = blockIdx.x * blockDim.x + threadIdx.x;
    const int total = NK * H * W;
    if (idx < total) {
        int k = idx / (H * W);
        d_dog[idx] = (d_g[idx] - d_g[idx + H*W]) * d_sig[k];
    }
}

// ---------------------------------------------------------------
// Peak test: center > THRESH and >= all 26 neighbors (== window max).
// Border-excluded: k in [1,11], y,x in [1,510]. Warp ballot -> bit mask.
// ---------------------------------------------------------------
__global__ void peak_k() {
    int k    = blockIdx.z;
    int y    = blockIdx.y * 8 + threadIdx.y;
    int xw   = blockIdx.x;
    int lane = threadIdx.x;
    int x    = xw * 32 + lane;
    bool p = false;
    if (k >= 1 && k <= NK-2 && y >= 1 && y <= H-2 && x >= 1 && x <= W-2) {
        float c = d_dog[(k*H + y)*W + x];
        if (c > THRESH) {
            p = true;
            #pragma unroll
            for (int dk = -1; dk <= 1 && p; dk++)
                #pragma unroll
                for (int dy = -1; dy <= 1 && p; dy++)
                    #pragma unroll
                    for (int dx = -1; dx <= 1; dx++) {
                        if ((dk | dy | dx) == 0) continue;
                        if (d_dog[((k+dk)*H + (y+dy))*W + (x+dx)] > c) { p = false; break; }
                    }
        }
    }
    unsigned wmask = __ballot_sync(0xFFFFFFFFu, p);
    if (lane == 0) d_maskw[(k*H + y)*16 + xw] = wmask;
}

// ---------------------------------------------------------------
// Per-row popcounts
// ---------------------------------------------------------------
__global__ void rowcnt_k() {
    int rid = blockIdx.x * blockDim.x + threadIdx.x;
    if (rid < NROWS) {
        int c = 0;
        #pragma unroll
        for (int w = 0; w < 16; w++) c += __popc(d_maskw[rid*16 + w]);
        d_rowcnt[rid] = c;
    }
}

// ---------------------------------------------------------------
// Single-block exclusive scan over 6656 row counts (row-major order)
// ---------------------------------------------------------------
__global__ void scan_k() {
    const int PER = (NROWS + 1023) / 1024;   // 7
    int tid = threadIdx.x;
    int vals[PER];
    int local = 0;
    int start = tid * PER;
    #pragma unroll
    for (int j = 0; j < PER; j++) {
        int idx = start + j;
        int v = (idx < NROWS) ? d_rowcnt[idx] : 0;
        vals[j] = v;
        local += v;
    }
    __shared__ int sh[1024];
    sh[tid] = local;
    __syncthreads();
    for (int off = 1; off < 1024; off <<= 1) {
        int v = (tid >= off) ? sh[tid - off] : 0;
        __syncthreads();
        sh[tid] += v;
        __syncthreads();
    }
    int run = sh[tid] - local;   // exclusive prefix of this thread's chunk
    #pragma unroll
    for (int j = 0; j < PER; j++) {
        int idx = start + j;
        if (idx < NROWS) { d_rowcnt[idx] = run; run += vals[j]; }
    }
}

// ---------------------------------------------------------------
// Fill output with nonzero()'s fill rows: indices (0,0,0) -> (sigma0, 0, 0)
// ---------------------------------------------------------------
__global__ void fill_k(float* __restrict__ out) {
    int i = blockIdx.x * blockDim.x + threadIdx.x;
    if (i < MAXPEAKS) {
        out[3*i]     = d_sig[0];
        out[3*i + 1] = 0.f;
        out[3*i + 2] = 0.f;
    }
}

// ---------------------------------------------------------------
// Scatter peaks in row-major (k, y, x) order
// ---------------------------------------------------------------
__global__ void write_k(float* __restrict__ out) {
    int rid  = blockIdx.x;
    int lane = threadIdx.x;
    int k = rid >> 9, y = rid & 511;
    int run = d_rowcnt[rid];
    float sg = d_sig[k];
    for (int w = 0; w < 16; w++) {
        unsigned word = d_maskw[rid*16 + w];
        if (word) {
            if ((word >> lane) & 1u) {
                int idx = run + __popc(word & ((1u << lane) - 1u));
                if (idx < MAXPEAKS) {
                    out[3*idx]     = sg;
                    out[3*idx + 1] = (float)y;
                    out[3*idx + 2] = (float)(w*32 + lane);
                }
            }
            run += __popc(word);
        }
    }
}

extern "C" void kernel_launch(void* const* d_in, const int* in_sizes, int n_in,
                              void* d_out, int out_size) {
    // Select inputs by element count (robust to metadata ordering):
    //   x: 512*512 = 262144, weight: 14*87*87 = 105966, sigma_list: 14
    const float* x     = nullptr;
    const float* sigma = nullptr;
    for (int i = 0; i < n_in; i++) {
        if (in_sizes[i] == H * W)   x     = (const float*)d_in[i];
        else if (in_sizes[i] == NS) sigma = (const float*)d_in[i];
    }
    if (!x)     x     = (const float*)d_in[0];
    if (!sigma) sigma = (const float*)d_in[n_in - 1];

    float* out = (float*)d_out;                   // [32768, 3]

    build_kernels_k<<<NS, 128>>>(sigma);
    hblur_k<<<dim3(H, NS), 256>>>(x);
    vblur_k<<<dim3(W/VTX, H/VTY, NS), dim3(VTX, 8)>>>();
    dog_k<<<(NK*H*W + 255)/256, 256>>>();
    peak_k<<<dim3(16, H/8, NK), dim3(32, 8)>>>();
    rowcnt_k<<<(NROWS + 255)/256, 256>>>();
    scan_k<<<1, 1024>>>();
    fill_k<<<(MAXPEAKS + 255)/256, 256>>>(out);
    write_k<<<NROWS, 32>>>(out);
}

// round 4
// speedup vs baseline: 2.6172x; 2.6172x over previous
#include <cuda_runtime.h>
#include <math.h>

#define H 512
#define W 512
#define NS 14            // number of gaussian scales (K+1)
#define NK 13            // number of DoG planes (K)
#define MAXR 43
#define NROWS (NK*H)
#define THRESH 0.001f
#define MAXPEAKS 32768

// ---- scratch (static device memory; no allocations allowed) ----
__device__ float2 d_tmp[NS*H*W];      // after horizontal blur (df64 hi/lo)
__device__ float  d_g[NS*H*W];        // gaussian pyramid, fp32 (matches ref's g)
__device__ float  d_dog[NK*H*W];      // DoG * sigma (fp32, from fp32 g like ref)
__device__ float2 d_k1d[NS*96];       // 1D kernels as df64 pairs (zero padded)
__device__ int    d_rad[NS];
__device__ float  d_sig[NS];
__device__ unsigned d_maskw[NROWS*16];// 512-bit peak mask per (k,y) row
__device__ int    d_rowcnt[NROWS];    // counts, then exclusive offsets

// ---- df64 compensated accumulation (Ogita-Rump dot2 style) ----
// All ops via _rn intrinsics so -fmad contraction cannot break the EFTs.
__device__ __forceinline__ void df_accum(float& hi, float& lo, float p, float ep) {
    float t  = __fadd_rn(hi, p);
    float bp = __fsub_rn(t, hi);
    float e  = __fadd_rn(__fsub_rn(hi, __fsub_rn(t, bp)), __fsub_rn(p, bp));
    hi = t;
    lo = __fadd_rn(lo, __fadd_rn(e, ep));
}

// ---------------------------------------------------------------
// Build normalized 1D gaussian kernels in fp64, split to df64 pairs.
// g1[j] = exp(-(((j-mean)/(2s))^2)) / sum  (prefactor cancels).
// 2D kernel = outer(g1,g1) => separable H+V conv == full 2D conv.
// ---------------------------------------------------------------
__global__ void build_kernels_k(const float* __restrict__ sigma_list) {
    int i   = blockIdx.x;
    int tid = threadIdx.x;      // 128 threads
    float sf = sigma_list[i];
    double s = (double)sf;
    int r   = (int)floor(4.0 * s + 0.5);   // TRUNCATE=4
    int n   = 2 * r + 1;
    __shared__ double tmp[96];
    __shared__ double ssum;
    if (tid < n) {
        double mean = 0.5 * (double)(n - 1);
        double d = ((double)tid - mean) / (2.0 * s);
        tmp[tid] = exp(-(d * d));
    }
    __syncthreads();
    if (tid == 0) {
        double acc = 0.0;
        for (int j = 0; j < n; j++) acc += tmp[j];
        ssum = acc;
        d_rad[i] = r;
        d_sig[i] = sf;
    }
    __syncthreads();
    if (tid < 96) {
        double v = (tid < n) ? tmp[tid] / ssum : 0.0;
        float vh = (float)v;
        float vl = (float)(v - (double)vh);
        d_k1d[i*96 + tid] = make_float2(vh, vl);
    }
}

// ---------------------------------------------------------------
// Horizontal pass (df64 accumulation): one block per (row, scale).
// ---------------------------------------------------------------
__global__ void hblur_k(const float* __restrict__ x) {
    int y  = blockIdx.x;
    int sc = blockIdx.y;
    int r  = d_rad[sc];
    int n  = 2 * r + 1;
    __shared__ float  srow[W + 2*MAXR];
    __shared__ float2 sk[96];
    int tid = threadIdx.x;
    for (int i = tid; i < W + 2*r; i += blockDim.x) {
        int xx = i - r;
        srow[i] = (xx >= 0 && xx < W) ? x[y*W + xx] : 0.f;
    }
    for (int i = tid; i < n; i += blockDim.x) sk[i] = d_k1d[sc*96 + i];
    __syncthreads();
    float2* outp = d_tmp + (size_t)(sc*H + y) * W;
    for (int xo = tid; xo < W; xo += blockDim.x) {
        float hi = 0.f, lo = 0.f;
        for (int d = 0; d < n; d++) {
            float a = srow[xo + d];
            float2 k = sk[d];
            float p  = __fmul_rn(a, k.x);
            float ep = __fmaf_rn(a, k.x, -p);
            ep = __fmaf_rn(a, k.y, ep);
            df_accum(hi, lo, p, ep);
        }
        outp[xo] = make_float2(hi, lo);
    }
}

// ---------------------------------------------------------------
// Vertical pass (df64): 32-wide x-strip, 32-row output tile per block.
// Result rounded to fp32 (matches reference's materialized fp32 g).
// ---------------------------------------------------------------
#define VTX 32
#define VTY 32
__global__ void vblur_k() {
    int sc = blockIdx.z;
    int x0 = blockIdx.x * VTX;
    int y0 = blockIdx.y * VTY;
    int r  = d_rad[sc];
    int n  = 2 * r + 1;
    __shared__ float2 tile[(VTY + 2*MAXR) * VTX];   // 118*32*8 = 30208 B
    __shared__ float2 sk[96];
    int tid = threadIdx.x + threadIdx.y * VTX;      // blockDim (32,8) = 256
    int nth = VTX * 8;
    int rows = VTY + 2 * r;
    const float2* inp = d_tmp + (size_t)sc * H * W;
    for (int i = tid; i < rows * VTX; i += nth) {
        int rr = i / VTX, cc = i % VTX;
        int gy = y0 - r + rr;
        tile[i] = (gy >= 0 && gy < H) ? inp[gy*W + x0 + cc] : make_float2(0.f, 0.f);
    }
    for (int i = tid; i < n; i += nth) sk[i] = d_k1d[sc*96 + i];
    __syncthreads();
    float* outp = d_g + (size_t)sc * H * W;
    int tx = threadIdx.x;
    for (int yo = threadIdx.y; yo < VTY; yo += 8) {
        float hi = 0.f, lo = 0.f;
        for (int d = 0; d < n; d++) {
            float2 a = tile[(yo + d)*VTX + tx];
            float2 k = sk[d];
            float p  = __fmul_rn(a.x, k.x);
            float ep = __fmaf_rn(a.x, k.x, -p);
            ep = __fmaf_rn(a.x, k.y, ep);
            ep = __fmaf_rn(a.y, k.x, ep);
            df_accum(hi, lo, p, ep);
        }
        outp[(y0 + yo)*W + x0 + tx] = __fadd_rn(hi, lo);
    }
}

// ---------------------------------------------------------------
// DoG in fp32, exactly like reference: dog[k] = (g[k]-g[k+1])*sigma[k]
// ---------------------------------------------------------------
__global__ void dog_k() {
    int idx = blockIdx.x * blockDim.x + threadIdx.x;
    const int total = NK * H * W;
    if (idx < total) {
        int k = idx / (H * W);
        d_dog[idx] = (d_g[idx] - d_g[idx + H*W]) * d_sig[k];
    }
}

// ---------------------------------------------------------------
// Peak test: center > THRESH and >= all 26 neighbors (== window max).
// Border-excluded: k in [1,11], y,x in [1,510]. Warp ballot -> bit mask.
// ---------------------------------------------------------------
__global__ void peak_k() {
    int k    = blockIdx.z;
    int y    = blockIdx.y * 8 + threadIdx.y;
    int xw   = blockIdx.x;
    int lane = threadIdx.x;
    int x    = xw * 32 + lane;
    bool p = false;
    if (k >= 1 && k <= NK-2 && y >= 1 && y <= H-2 && x >= 1 && x <= W-2) {
        float c = d_dog[(k*H + y)*W + x];
        if (c > THRESH) {
            p = true;
            #pragma unroll
            for (int dk = -1; dk <= 1 && p; dk++)
                #pragma unroll
                for (int dy = -1; dy <= 1 && p; dy++)
                    #pragma unroll
                    for (int dx = -1; dx <= 1; dx++) {
                        if ((dk | dy | dx) == 0) continue;
                        if (d_dog[((k+dk)*H + (y+dy))*W + (x+dx)] > c) { p = false; break; }
                    }
        }
    }
    unsigned wmask = __ballot_sync(0xFFFFFFFFu, p);
    if (lane == 0) d_maskw[(k*H + y)*16 + xw] = wmask;
}

// ---------------------------------------------------------------
// Per-row popcounts
// ---------------------------------------------------------------
__global__ void rowcnt_k() {
    int rid = blockIdx.x * blockDim.x + threadIdx.x;
    if (rid < NROWS) {
        int c = 0;
        #pragma unroll
        for (int w = 0; w < 16; w++) c += __popc(d_maskw[rid*16 + w]);
        d_rowcnt[rid] = c;
    }
}

// ---------------------------------------------------------------
// Single-block exclusive scan over 6656 row counts (row-major order)
// ---------------------------------------------------------------
__global__ void scan_k() {
    const int PER = (NROWS + 1023) / 1024;   // 7
    int tid = threadIdx.x;
    int vals[PER];
    int local = 0;
    int start = tid * PER;
    #pragma unroll
    for (int j = 0; j < PER; j++) {
        int idx = start + j;
        int v = (idx < NROWS) ? d_rowcnt[idx] : 0;
        vals[j] = v;
        local += v;
    }
    __shared__ int sh[1024];
    sh[tid] = local;
    __syncthreads();
    for (int off = 1; off < 1024; off <<= 1) {
        int v = (tid >= off) ? sh[tid - off] : 0;
        __syncthreads();
        sh[tid] += v;
        __syncthreads();
    }
    int run = sh[tid] - local;   // exclusive prefix of this thread's chunk
    #pragma unroll
    for (int j = 0; j < PER; j++) {
        int idx = start + j;
        if (idx < NROWS) { d_rowcnt[idx] = run; run += vals[j]; }
    }
}

// ---------------------------------------------------------------
// Fill output with nonzero()'s fill rows: indices (0,0,0) -> (sigma0, 0, 0)
// ---------------------------------------------------------------
__global__ void fill_k(float* __restrict__ out) {
    int i = blockIdx.x * blockDim.x + threadIdx.x;
    if (i < MAXPEAKS) {
        out[3*i]     = d_sig[0];
        out[3*i + 1] = 0.f;
        out[3*i + 2] = 0.f;
    }
}

// ---------------------------------------------------------------
// Scatter peaks in row-major (k, y, x) order
// ---------------------------------------------------------------
__global__ void write_k(float* __restrict__ out) {
    int rid  = blockIdx.x;
    int lane = threadIdx.x;
    int k = rid >> 9, y = rid & 511;
    int run = d_rowcnt[rid];
    float sg = d_sig[k];
    for (int w = 0; w < 16; w++) {
        unsigned word = d_maskw[rid*16 + w];
        if (word) {
            if ((word >> lane) & 1u) {
                int idx = run + __popc(word & ((1u << lane) - 1u));
                if (idx < MAXPEAKS) {
                    out[3*idx]     = sg;
                    out[3*idx + 1] = (float)y;
                    out[3*idx + 2] = (float)(w*32 + lane);
                }
            }
            run += __popc(word);
        }
    }
}

extern "C" void kernel_launch(void* const* d_in, const int* in_sizes, int n_in,
                              void* d_out, int out_size) {
    // Select inputs by element count (robust to metadata ordering):
    //   x: 512*512 = 262144, weight: 14*87*87 = 105966, sigma_list: 14
    const float* x     = nullptr;
    const float* sigma = nullptr;
    for (int i = 0; i < n_in; i++) {
        if (in_sizes[i] == H * W)   x     = (const float*)d_in[i];
        else if (in_sizes[i] == NS) sigma = (const float*)d_in[i];
    }
    if (!x)     x     = (const float*)d_in[0];
    if (!sigma) sigma = (const float*)d_in[n_in - 1];

    float* out = (float*)d_out;                   // [32768, 3]

    build_kernels_k<<<NS, 128>>>(sigma);
    hblur_k<<<dim3(H, NS), 256>>>(x);
    vblur_k<<<dim3(W/VTX, H/VTY, NS), dim3(VTX, 8)>>>();
    dog_k<<<(NK*H*W + 255)/256, 256>>>();
    peak_k<<<dim3(16, H/8, NK), dim3(32, 8)>>>();
    rowcnt_k<<<(NROWS + 255)/256, 256>>>();
    scan_k<<<1, 1024>>>();
    fill_k<<<(MAXPEAKS + 255)/256, 256>>>(out);
    write_k<<<NROWS, 32>>>(out);
}

// round 5
// speedup vs baseline: 5.3684x; 2.0512x over previous
#include <cuda_runtime.h>
#include <math.h>

#define H 512
#define W 512
#define NS 14            // number of gaussian scales (K+1)
#define NK 13            // number of DoG planes (K)
#define MAXR 43
#define NROWS (NK*H)
#define THRESH 0.001f
#define MAXPEAKS 32768

// ---- scratch (static device memory; no allocations allowed) ----
__device__ float2 d_tmp[NS*H*W];      // after horizontal blur (df64 hi/lo)
__device__ float  d_g[NS*H*W];        // gaussian pyramid, fp32 (matches ref's g)
__device__ float  d_dog[NK*H*W];      // DoG * sigma (fp32, from fp32 g like ref)
__device__ float2 d_k1d[NS*96];       // 1D kernels as df64 pairs (zero padded)
__device__ int    d_rad[NS];
__device__ float  d_sig[NS];
__device__ unsigned d_maskw[NROWS*16];// 512-bit peak mask per (k,y) row
__device__ int    d_rowcnt[NROWS];    // counts, then exclusive offsets

// ---------------------------------------------------------------
// Build normalized 1D gaussian kernels in fp64, split to df64 pairs.
// ---------------------------------------------------------------
__global__ void build_kernels_k(const float* __restrict__ sigma_list) {
    int i   = blockIdx.x;
    int tid = threadIdx.x;      // 128 threads
    float sf = sigma_list[i];
    double s = (double)sf;
    int r   = (int)floor(4.0 * s + 0.5);   // TRUNCATE=4
    int n   = 2 * r + 1;
    __shared__ double tmp[96];
    __shared__ double ssum;
    if (tid < n) {
        double mean = 0.5 * (double)(n - 1);
        double d = ((double)tid - mean) / (2.0 * s);
        tmp[tid] = exp(-(d * d));
    }
    __syncthreads();
    if (tid == 0) {
        double acc = 0.0;
        for (int j = 0; j < n; j++) acc += tmp[j];
        ssum = acc;
        d_rad[i] = r;
        d_sig[i] = sf;
    }
    __syncthreads();
    if (tid < 96) {
        double v = (tid < n) ? tmp[tid] / ssum : 0.0;
        float vh = (float)v;
        float vl = (float)(v - (double)vh);
        d_k1d[i*96 + tid] = make_float2(vh, vl);
    }
}

// ---------------------------------------------------------------
// Horizontal pass. df64 via exact-product split + ANCHORED Fast2Sum:
// all products p>=0 and sum(p)<1, hi seeded to 2.0 so hi>=2>p always
// -> Fast2Sum error extraction exact; final (hi-2) exact (Sterbenz).
// 4 consecutive outputs per thread, sliding register window.
// blockDim 128, grid (H, NS).
// ---------------------------------------------------------------
__global__ void hblur_k(const float* __restrict__ x) {
    int y  = blockIdx.x;
    int sc = blockIdx.y;
    int r  = d_rad[sc];
    int n  = 2 * r + 1;
    __shared__ float  srow[W + 2*MAXR + 4];
    __shared__ float2 sk[96];
    int tid = threadIdx.x;
    for (int i = tid; i < W + 2*r; i += 128) {
        int xx = i - r;
        srow[i] = (xx >= 0 && xx < W) ? x[y*W + xx] : 0.f;
    }
    for (int i = tid; i < n; i += 128) sk[i] = d_k1d[sc*96 + i];
    __syncthreads();

    int xo = tid * 4;
    float wv[4];
    #pragma unroll
    for (int j = 0; j < 4; j++) wv[j] = srow[xo + j];
    float hi[4] = {2.f, 2.f, 2.f, 2.f};
    float lo[4] = {0.f, 0.f, 0.f, 0.f};

    #pragma unroll 4
    for (int d = 0; d < n; d++) {
        float2 k = sk[d];
        #pragma unroll
        for (int j = 0; j < 4; j++) {
            float a  = wv[j];
            float p  = __fmul_rn(a, k.x);
            float ep = __fmaf_rn(a, k.x, -p);     // exact product residual
            ep = __fmaf_rn(a, k.y, ep);           // + low part of coeff
            float t = __fadd_rn(hi[j], p);        // Fast2Sum (hi >= 2 > p)
            float e = __fsub_rn(p, __fsub_rn(t, hi[j]));
            hi[j] = t;
            lo[j] = __fadd_rn(lo[j], __fadd_rn(e, ep));
        }
        wv[0] = wv[1]; wv[1] = wv[2]; wv[2] = wv[3];
        wv[3] = srow[xo + d + 4];
    }
    float2* outp = d_tmp + (size_t)(sc*H + y) * W + xo;
    #pragma unroll
    for (int j = 0; j < 4; j++)
        outp[j] = make_float2(__fsub_rn(hi[j], 2.f), lo[j]);
}

// ---------------------------------------------------------------
// Vertical pass: 32-wide x-strip, 32 output rows/block, 4 per thread.
// Same anchored Fast2Sum scheme; inputs are df64 pairs.
// blockDim (32,8), grid (16,16,NS).
// ---------------------------------------------------------------
#define VTX 32
#define VTY 32
__global__ void vblur_k() {
    int sc = blockIdx.z;
    int x0 = blockIdx.x * VTX;
    int y0 = blockIdx.y * VTY;
    int r  = d_rad[sc];
    int n  = 2 * r + 1;
    __shared__ float2 tile[(VTY + 2*MAXR + 2) * VTX];
    __shared__ float2 sk[96];
    int tx  = threadIdx.x;
    int tid = tx + threadIdx.y * VTX;   // 256 threads
    int rows = VTY + 2 * r;
    const float2* inp = d_tmp + (size_t)sc * H * W;
    for (int i = tid; i < rows * VTX; i += 256) {
        int rr = i / VTX, cc = i % VTX;
        int gy = y0 - r + rr;
        tile[i] = (gy >= 0 && gy < H) ? inp[gy*W + x0 + cc] : make_float2(0.f, 0.f);
    }
    for (int i = tid; i < n; i += 256) sk[i] = d_k1d[sc*96 + i];
    __syncthreads();

    int yo = threadIdx.y * 4;
    float2 wv[4];
    #pragma unroll
    for (int j = 0; j < 4; j++) wv[j] = tile[(yo + j)*VTX + tx];
    float hi[4] = {2.f, 2.f, 2.f, 2.f};
    float lo[4] = {0.f, 0.f, 0.f, 0.f};

    #pragma unroll 4
    for (int d = 0; d < n; d++) {
        float2 k = sk[d];
        #pragma unroll
        for (int j = 0; j < 4; j++) {
            float2 a = wv[j];
            float p  = __fmul_rn(a.x, k.x);
            float ep = __fmaf_rn(a.x, k.x, -p);
            ep = __fmaf_rn(a.x, k.y, ep);
            ep = __fmaf_rn(a.y, k.x, ep);
            float t = __fadd_rn(hi[j], p);
            float e = __fsub_rn(p, __fsub_rn(t, hi[j]));
            hi[j] = t;
            lo[j] = __fadd_rn(lo[j], __fadd_rn(e, ep));
        }
        wv[0] = wv[1]; wv[1] = wv[2]; wv[2] = wv[3];
        wv[3] = tile[(yo + d + 4)*VTX + tx];
    }
    float* outp = d_g + (size_t)sc * H * W;
    #pragma unroll
    for (int j = 0; j < 4; j++)
        outp[(y0 + yo + j)*W + x0 + tx] =
            __fadd_rn(__fsub_rn(hi[j], 2.f), lo[j]);
}

// ---------------------------------------------------------------
// DoG in fp32 (float4 vectorized): dog[k] = (g[k]-g[k+1])*sigma[k]
// ---------------------------------------------------------------
__global__ void dog_k() {
    int idx = blockIdx.x * blockDim.x + threadIdx.x;
    const int total4 = NK * H * W / 4;
    if (idx < total4) {
        int k = idx / (H * W / 4);
        float4 a = ((const float4*)d_g)[idx];
        float4 b = ((const float4*)d_g)[idx + H*W/4];
        float s = d_sig[k];
        float4 o;
        o.x = (a.x - b.x) * s;
        o.y = (a.y - b.y) * s;
        o.z = (a.z - b.z) * s;
        o.w = (a.w - b.w) * s;
        ((float4*)d_dog)[idx] = o;
    }
}

// ---------------------------------------------------------------
// Peak test: center > THRESH and >= all 26 neighbors.
// Border-excluded: k in [1,11], y,x in [1,510]. Ballot -> bit mask.
// ---------------------------------------------------------------
__global__ void peak_k() {
    int k    = blockIdx.z;
    int y    = blockIdx.y * 8 + threadIdx.y;
    int xw   = blockIdx.x;
    int lane = threadIdx.x;
    int x    = xw * 32 + lane;
    bool p = false;
    if (k >= 1 && k <= NK-2 && y >= 1 && y <= H-2 && x >= 1 && x <= W-2) {
        float c = d_dog[(k*H + y)*W + x];
        if (c > THRESH) {
            p = true;
            #pragma unroll
            for (int dk = -1; dk <= 1 && p; dk++)
                #pragma unroll
                for (int dy = -1; dy <= 1 && p; dy++)
                    #pragma unroll
                    for (int dx = -1; dx <= 1; dx++) {
                        if ((dk | dy | dx) == 0) continue;
                        if (d_dog[((k+dk)*H + (y+dy))*W + (x+dx)] > c) { p = false; break; }
                    }
        }
    }
    unsigned wmask = __ballot_sync(0xFFFFFFFFu, p);
    if (lane == 0) d_maskw[(k*H + y)*16 + xw] = wmask;
}

__global__ void rowcnt_k() {
    int rid = blockIdx.x * blockDim.x + threadIdx.x;
    if (rid < NROWS) {
        int c = 0;
        #pragma unroll
        for (int w = 0; w < 16; w++) c += __popc(d_maskw[rid*16 + w]);
        d_rowcnt[rid] = c;
    }
}

__global__ void scan_k() {
    const int PER = (NROWS + 1023) / 1024;   // 7
    int tid = threadIdx.x;
    int vals[PER];
    int local = 0;
    int start = tid * PER;
    #pragma unroll
    for (int j = 0; j < PER; j++) {
        int idx = start + j;
        int v = (idx < NROWS) ? d_rowcnt[idx] : 0;
        vals[j] = v;
        local += v;
    }
    __shared__ int sh[1024];
    sh[tid] = local;
    __syncthreads();
    for (int off = 1; off < 1024; off <<= 1) {
        int v = (tid >= off) ? sh[tid - off] : 0;
        __syncthreads();
        sh[tid] += v;
        __syncthreads();
    }
    int run = sh[tid] - local;
    #pragma unroll
    for (int j = 0; j < PER; j++) {
        int idx = start + j;
        if (idx < NROWS) { d_rowcnt[idx] = run; run += vals[j]; }
    }
}

__global__ void fill_k(float* __restrict__ out) {
    int i = blockIdx.x * blockDim.x + threadIdx.x;
    if (i < MAXPEAKS) {
        out[3*i]     = d_sig[0];
        out[3*i + 1] = 0.f;
        out[3*i + 2] = 0.f;
    }
}

__global__ void write_k(float* __restrict__ out) {
    int rid  = blockIdx.x;
    int lane = threadIdx.x;
    int k = rid >> 9, y = rid & 511;
    int run = d_rowcnt[rid];
    float sg = d_sig[k];
    for (int w = 0; w < 16; w++) {
        unsigned word = d_maskw[rid*16 + w];
        if (word) {
            if ((word >> lane) & 1u) {
                int idx = run + __popc(word & ((1u << lane) - 1u));
                if (idx < MAXPEAKS) {
                    out[3*idx]     = sg;
                    out[3*idx + 1] = (float)y;
                    out[3*idx + 2] = (float)(w*32 + lane);
                }
            }
            run += __popc(word);
        }
    }
}

extern "C" void kernel_launch(void* const* d_in, const int* in_sizes, int n_in,
                              void* d_out, int out_size) {
    const float* x     = nullptr;
    const float* sigma = nullptr;
    for (int i = 0; i < n_in; i++) {
        if (in_sizes[i] == H * W)   x     = (const float*)d_in[i];
        else if (in_sizes[i] == NS) sigma = (const float*)d_in[i];
    }
    if (!x)     x     = (const float*)d_in[0];
    if (!sigma) sigma = (const float*)d_in[n_in - 1];

    float* out = (float*)d_out;                   // [32768, 3]

    build_kernels_k<<<NS, 128>>>(sigma);
    hblur_k<<<dim3(H, NS), 128>>>(x);
    vblur_k<<<dim3(W/VTX, H/VTY, NS), dim3(VTX, 8)>>>();
    dog_k<<<(NK*H*W/4 + 255)/256, 256>>>();
    peak_k<<<dim3(16, H/8, NK), dim3(32, 8)>>>();
    rowcnt_k<<<(NROWS + 255)/256, 256>>>();
    scan_k<<<1, 1024>>>();
    fill_k<<<(MAXPEAKS + 255)/256, 256>>>(out);
    write_k<<<NROWS, 32>>>(out);
}